// round 3
// baseline (speedup 1.0000x reference)
#include <cuda_runtime.h>
#include <math.h>

#define TDIM 1024
#define CDIM 768
#define PH 32
#define PW 32
#define NHEAD 12
#define HS 64
#define NR (8*1024)

__device__ float g_xx [NR*CDIM];
__device__ float g_xxx[NR*CDIM];
__device__ float g_t  [NR*160];
__device__ float g_xw [NR*CDIM];
__device__ float g_xk [NR*CDIM];
__device__ float g_xv [NR*CDIM];
__device__ float g_xr [NR*CDIM];
__device__ float g_xg [NR*CDIM];
__device__ float g_r  [NR*CDIM];
__device__ float g_k  [NR*CDIM];
__device__ float g_v  [NR*CDIM];
__device__ float g_g  [NR*CDIM];
__device__ float g_h1 [NR*64];
__device__ float g_w  [NR*CDIM];
__device__ float g_y  [NR*CDIM];
__device__ float g_yg [NR*CDIM];

// ---------------- K1: q_shift + maa_x mix ----------------
__global__ void shift_mix_kernel(const float* __restrict__ x,
                                 const float* __restrict__ maa_x,
                                 float* __restrict__ xx, float* __restrict__ xxx,
                                 int total)
{
    int idx = blockIdx.x * blockDim.x + threadIdx.x;
    if (idx >= total) return;
    int c = idx % CDIM;
    int t = (idx / CDIM) % TDIM;
    int b = idx / (CDIM * TDIM);
    int d  = c & (HS - 1);
    int hh = t >> 5, ww = t & 31;
    float sh = 0.f;
    int st = -1;
    if (d < 16)      { if (ww >= 1)      st = t - 1;  }
    else if (d < 32) { if (ww < PW - 1)  st = t + 1;  }
    else if (d < 48) { if (hh >= 1)      st = t - PW; }
    else             { if (hh < PH - 1)  st = t + PW; }
    if (st >= 0) sh = x[((size_t)b * TDIM + st) * CDIM + c];
    float xv = x[idx];
    float dd = sh - xv;
    xx[idx]  = dd;
    xxx[idx] = xv + dd * maa_x[c];
}

// ---------------- generic fp32 GEMM 128x128x16 ----------------
// EPI: 0 none, 1 tanh, 2 relu, 3 +bias[n]
template<int EPI>
__device__ __forceinline__ float epi_f(float a, const float* bias, int n) {
    if (EPI == 1) return tanhf(a);
    if (EPI == 2) return fmaxf(a, 0.f);
    if (EPI == 3) return a + bias[n];
    return a;
}

template<int EPI, bool BT>
__global__ __launch_bounds__(256, 2) void gemm_kernel(
    const float* __restrict__ A, int lda,
    const float* __restrict__ Bm,
    float* __restrict__ Cm, int ldc,
    int N, int K, const float* __restrict__ bias)
{
    __shared__ __align__(16) float As[16][128];
    __shared__ __align__(16) float Bs[16][132];
    int tid = threadIdx.x;
    int m0 = blockIdx.y * 128, n0 = blockIdx.x * 128;
    int tx = tid & 15, ty = tid >> 4;

    float acc[8][8];
#pragma unroll
    for (int i = 0; i < 8; i++)
#pragma unroll
        for (int j = 0; j < 8; j++) acc[i][j] = 0.f;

    for (int k0 = 0; k0 < K; k0 += 16) {
#pragma unroll
        for (int p = 0; p < 2; p++) {
            int idx = tid + p * 256;
            int r = idx >> 2, kk = (idx & 3) << 2;
            const float4 v = *(const float4*)(A + (size_t)(m0 + r) * lda + k0 + kk);
            As[kk + 0][r] = v.x; As[kk + 1][r] = v.y;
            As[kk + 2][r] = v.z; As[kk + 3][r] = v.w;
        }
        if (BT) {
#pragma unroll
            for (int p = 0; p < 2; p++) {
                int idx = tid + p * 256;
                int r = idx >> 2, kk = (idx & 3) << 2;
                float4 v = make_float4(0.f, 0.f, 0.f, 0.f);
                if (n0 + r < N)
                    v = *(const float4*)(Bm + (size_t)(n0 + r) * K + k0 + kk);
                Bs[kk + 0][r] = v.x; Bs[kk + 1][r] = v.y;
                Bs[kk + 2][r] = v.z; Bs[kk + 3][r] = v.w;
            }
        } else {
#pragma unroll
            for (int p = 0; p < 2; p++) {
                int idx = tid + p * 256;
                int kk = idx >> 5, nn = (idx & 31) << 2;
                float4 v = make_float4(0.f, 0.f, 0.f, 0.f);
                if (n0 + nn < N)
                    v = *(const float4*)(Bm + (size_t)(k0 + kk) * N + n0 + nn);
                Bs[kk][nn + 0] = v.x; Bs[kk][nn + 1] = v.y;
                Bs[kk][nn + 2] = v.z; Bs[kk][nn + 3] = v.w;
            }
        }
        __syncthreads();
#pragma unroll
        for (int kk = 0; kk < 16; kk++) {
            float a[8], b[8];
            *(float4*)&a[0] = *(const float4*)&As[kk][ty * 8];
            *(float4*)&a[4] = *(const float4*)&As[kk][ty * 8 + 4];
            *(float4*)&b[0] = *(const float4*)&Bs[kk][tx * 8];
            *(float4*)&b[4] = *(const float4*)&Bs[kk][tx * 8 + 4];
#pragma unroll
            for (int i = 0; i < 8; i++)
#pragma unroll
                for (int j = 0; j < 8; j++)
                    acc[i][j] += a[i] * b[j];
        }
        __syncthreads();
    }
#pragma unroll
    for (int i = 0; i < 8; i++) {
        int m = m0 + ty * 8 + i;
#pragma unroll
        for (int j4 = 0; j4 < 2; j4++) {
            int n = n0 + tx * 8 + j4 * 4;
            if (n < N) {
                float4 v;
                v.x = epi_f<EPI>(acc[i][j4 * 4 + 0], bias, n + 0);
                v.y = epi_f<EPI>(acc[i][j4 * 4 + 1], bias, n + 1);
                v.z = epi_f<EPI>(acc[i][j4 * 4 + 2], bias, n + 2);
                v.w = epi_f<EPI>(acc[i][j4 * 4 + 3], bias, n + 3);
                *(float4*)(Cm + (size_t)m * ldc + n) = v;
            }
        }
    }
}

// ---------------- K3: 5-way token-shift mixer ----------------
// smem: w2 tile [160][256] + t rows [8][160]
#define MIX5_SMEM ((160*256 + 8*160) * 4)
__global__ __launch_bounds__(256, 1) void mix5_kernel(
    const float* __restrict__ x, const float* __restrict__ xx,
    const float* __restrict__ t_arr, const float* __restrict__ w2,
    const float* __restrict__ mw, const float* __restrict__ mk,
    const float* __restrict__ mv, const float* __restrict__ mr,
    const float* __restrict__ mg,
    float* __restrict__ xw, float* __restrict__ xk, float* __restrict__ xv,
    float* __restrict__ xr, float* __restrict__ xg)
{
    extern __shared__ __align__(16) float sm[];
    float* w2s = sm;                 // [160][256]
    float* ts2 = sm + 160 * 256;     // [8][160]
    int tid = threadIdx.x;
    int c = blockIdx.x * 256 + tid;
    int rbase = blockIdx.y * 64;

    for (int j = 0; j < 160; j++) w2s[j * 256 + tid] = w2[j * CDIM + c];
    float cw = mw[c], ck = mk[c], cv = mv[c], cr = mr[c], cg = mg[c];
    __syncthreads();

#pragma unroll 1
    for (int grp = 0; grp < 8; grp++) {
        int row0 = rbase + grp * 8;
        for (int i = tid; i < 8 * 160; i += 256)
            ts2[i] = t_arr[(size_t)(row0 + i / 160) * 160 + (i % 160)];
        __syncthreads();

        float acc[8][5];
#pragma unroll
        for (int r = 0; r < 8; r++)
#pragma unroll
            for (int f = 0; f < 5; f++) acc[r][f] = 0.f;

#pragma unroll
        for (int f = 0; f < 5; f++) {
#pragma unroll 2
            for (int j4 = 0; j4 < 8; j4++) {
                int jb = f * 32 + j4 * 4;
                float w0 = w2s[(jb + 0) * 256 + tid];
                float w1 = w2s[(jb + 1) * 256 + tid];
                float w2v = w2s[(jb + 2) * 256 + tid];
                float w3 = w2s[(jb + 3) * 256 + tid];
#pragma unroll
                for (int r = 0; r < 8; r++) {
                    float4 tv = *(const float4*)&ts2[r * 160 + jb];
                    acc[r][f] += tv.x * w0 + tv.y * w1 + tv.z * w2v + tv.w * w3;
                }
            }
        }
#pragma unroll
        for (int r = 0; r < 8; r++) {
            size_t gi = (size_t)(row0 + r) * CDIM + c;
            float xval = x[gi], xxval = xx[gi];
            xw[gi] = xval + xxval * (cw + acc[r][0]);
            xk[gi] = xval + xxval * (ck + acc[r][1]);
            xv[gi] = xval + xxval * (cv + acc[r][2]);
            xr[gi] = xval + xxval * (cr + acc[r][3]);
            xg[gi] = xval + xxval * (cg + acc[r][4]);
        }
        __syncthreads();
    }
}

// ---------------- K4: WKV6 recurrence ----------------
__device__ __forceinline__ void cp16(void* dst, const void* src) {
    unsigned d = (unsigned)__cvta_generic_to_shared(dst);
    asm volatile("cp.async.cg.shared.global [%0], [%1], 16;" :: "r"(d), "l"(src) : "memory");
}

__device__ __forceinline__ void wkv_issue(int ci, float* rsb, float* ksb,
        float* vsb, float* wsb,
        const float* rp, const float* kp, const float* vp, const float* wpp,
        size_t base, int tid)
{
#pragma unroll
    for (int p = 0; p < 2; p++) {
        int idx = tid + p * 256;
        int arr = idx >> 7;
        int rem = idx & 127;
        int tc = rem >> 4, c4 = (rem & 15) << 2;
        size_t gofs = base + (size_t)(ci * 8 + tc) * CDIM + c4;
        float* dst; const float* src;
        if (arr == 0)      { dst = rsb + tc * 64 + c4; src = rp  + gofs; }
        else if (arr == 1) { dst = ksb + tc * 64 + c4; src = kp  + gofs; }
        else if (arr == 2) { dst = vsb + tc * 64 + c4; src = vp  + gofs; }
        else               { dst = wsb + tc * 64 + c4; src = wpp + gofs; }
        cp16(dst, src);
    }
    asm volatile("cp.async.commit_group;" ::: "memory");
}

__global__ __launch_bounds__(256, 1) void wkv6_kernel(
    const float* __restrict__ rp, const float* __restrict__ kp,
    const float* __restrict__ vp, const float* __restrict__ wp_,
    const float* __restrict__ up, float* __restrict__ yp)
{
    __shared__ __align__(16) float rs[2][512], ks[2][512], vs[2][512], ws[2][512];
    __shared__ float us[64], ruks[8];
    int tid = threadIdx.x;
    int b = blockIdx.x / NHEAD, h = blockIdx.x % NHEAD;
    size_t base = (size_t)b * TDIM * CDIM + h * HS;
    if (tid < 64) us[tid] = up[h * HS + tid];
    int i = tid >> 2, jq = tid & 3;
    int lane = tid & 31, warp = tid >> 5;

    float S[16];
#pragma unroll
    for (int q = 0; q < 16; q++) S[q] = 0.f;

    wkv_issue(0, rs[0], ks[0], vs[0], ws[0], rp, kp, vp, wp_, base, tid);

#pragma unroll 1
    for (int ci = 0; ci < TDIM / 8; ci++) {
        int buf = ci & 1;
        asm volatile("cp.async.wait_group 0;" ::: "memory");
        __syncthreads();
        for (int idx = tid; idx < 512; idx += 256)
            ws[buf][idx] = expf(-expf(ws[buf][idx]));
        {   // per-step scalar: sum_j r_j*u_j*k_j, warp w handles step w
            float p = rs[buf][warp * 64 + lane] * us[lane] * ks[buf][warp * 64 + lane]
                    + rs[buf][warp * 64 + 32 + lane] * us[32 + lane] * ks[buf][warp * 64 + 32 + lane];
#pragma unroll
            for (int o = 16; o; o >>= 1) p += __shfl_xor_sync(0xffffffffu, p, o);
            if (lane == 0) ruks[warp] = p;
        }
        __syncthreads();
        if (ci + 1 < TDIM / 8) {
            int nb = buf ^ 1;
            wkv_issue(ci + 1, rs[nb], ks[nb], vs[nb], ws[nb], rp, kp, vp, wp_, base, tid);
        }
#pragma unroll 1
        for (int tc = 0; tc < 8; tc++) {
            float vi = vs[buf][tc * 64 + i];
            const float4* r4 = (const float4*)&rs[buf][tc * 64 + jq * 16];
            const float4* k4 = (const float4*)&ks[buf][tc * 64 + jq * 16];
            const float4* w4 = (const float4*)&ws[buf][tc * 64 + jq * 16];
            float yps = 0.f;
#pragma unroll
            for (int q = 0; q < 4; q++) {
                float4 rv = r4[q], kv = k4[q], wv = w4[q];
                yps += rv.x * S[q * 4 + 0]; S[q * 4 + 0] = wv.x * S[q * 4 + 0] + kv.x * vi;
                yps += rv.y * S[q * 4 + 1]; S[q * 4 + 1] = wv.y * S[q * 4 + 1] + kv.y * vi;
                yps += rv.z * S[q * 4 + 2]; S[q * 4 + 2] = wv.z * S[q * 4 + 2] + kv.z * vi;
                yps += rv.w * S[q * 4 + 3]; S[q * 4 + 3] = wv.w * S[q * 4 + 3] + kv.w * vi;
            }
            yps += __shfl_xor_sync(0xffffffffu, yps, 1);
            yps += __shfl_xor_sync(0xffffffffu, yps, 2);
            if (jq == 0)
                yp[base + (size_t)(ci * 8 + tc) * CDIM + i] = yps + vi * ruks[tc];
        }
    }
}

// ---------------- K5: per-head GroupNorm * g ----------------
__global__ void gn_mul_kernel(const float* __restrict__ y,
                              const float* __restrict__ lw, const float* __restrict__ lb,
                              const float* __restrict__ g, float* __restrict__ out)
{
    int row = blockIdx.x;
    int warp = threadIdx.x >> 5, lane = threadIdx.x & 31;
    size_t o = (size_t)row * CDIM + warp * HS;
    float v0 = y[o + lane], v1 = y[o + 32 + lane];
    float s = v0 + v1, ss = v0 * v0 + v1 * v1;
#pragma unroll
    for (int off = 16; off; off >>= 1) {
        s  += __shfl_xor_sync(0xffffffffu, s,  off);
        ss += __shfl_xor_sync(0xffffffffu, ss, off);
    }
    float mean = s * (1.f / HS);
    float var  = ss * (1.f / HS) - mean * mean;
    float inv  = rsqrtf(var + 1e-5f);
    int c0 = warp * HS + lane, c1 = c0 + 32;
    float n0 = (v0 - mean) * inv * lw[c0] + lb[c0];
    float n1 = (v1 - mean) * inv * lw[c1] + lb[c1];
    out[o + lane]      = n0 * g[o + lane];
    out[o + 32 + lane] = n1 * g[o + 32 + lane];
}

// ---------------- launcher ----------------
extern "C" void kernel_launch(void* const* d_in, const int* in_sizes, int n_in,
                              void* d_out, int out_size)
{
    const float* x          = (const float*)d_in[0];
    const float* W_r        = (const float*)d_in[1];
    const float* W_k        = (const float*)d_in[2];
    const float* W_v        = (const float*)d_in[3];
    const float* W_g        = (const float*)d_in[4];
    const float* W_o        = (const float*)d_in[5];
    const float* maa_x      = (const float*)d_in[6];
    const float* maa_w      = (const float*)d_in[7];
    const float* maa_k      = (const float*)d_in[8];
    const float* maa_v      = (const float*)d_in[9];
    const float* maa_r      = (const float*)d_in[10];
    const float* maa_g      = (const float*)d_in[11];
    const float* maa_w1     = (const float*)d_in[12];
    const float* maa_w2     = (const float*)d_in[13];
    const float* time_decay = (const float*)d_in[14];
    const float* dec_w1     = (const float*)d_in[15];
    const float* dec_w2     = (const float*)d_in[16];
    const float* faaaa      = (const float*)d_in[17];
    const float* ln_w       = (const float*)d_in[18];
    const float* ln_b       = (const float*)d_in[19];
    float* out = (float*)d_out;

    float *xx, *xxx, *tb, *xw, *xk, *xv, *xr, *xg, *rb, *kb, *vb, *gb, *h1, *wb, *yb, *yg;
    cudaGetSymbolAddress((void**)&xx,  g_xx);
    cudaGetSymbolAddress((void**)&xxx, g_xxx);
    cudaGetSymbolAddress((void**)&tb,  g_t);
    cudaGetSymbolAddress((void**)&xw,  g_xw);
    cudaGetSymbolAddress((void**)&xk,  g_xk);
    cudaGetSymbolAddress((void**)&xv,  g_xv);
    cudaGetSymbolAddress((void**)&xr,  g_xr);
    cudaGetSymbolAddress((void**)&xg,  g_xg);
    cudaGetSymbolAddress((void**)&rb,  g_r);
    cudaGetSymbolAddress((void**)&kb,  g_k);
    cudaGetSymbolAddress((void**)&vb,  g_v);
    cudaGetSymbolAddress((void**)&gb,  g_g);
    cudaGetSymbolAddress((void**)&h1,  g_h1);
    cudaGetSymbolAddress((void**)&wb,  g_w);
    cudaGetSymbolAddress((void**)&yb,  g_y);
    cudaGetSymbolAddress((void**)&yg,  g_yg);

    int total = NR * CDIM;
    shift_mix_kernel<<<(total + 255) / 256, 256>>>(x, maa_x, xx, xxx, total);

    // t = tanh(xxx @ maa_w1)   [NR,160]
    {
        dim3 grid(2, NR / 128);
        gemm_kernel<1, false><<<grid, 256>>>(xxx, CDIM, maa_w1, tb, 160, 160, CDIM, nullptr);
    }

    // xw..xg via 5-way mixer
    cudaFuncSetAttribute(mix5_kernel, cudaFuncAttributeMaxDynamicSharedMemorySize, MIX5_SMEM);
    {
        dim3 grid(3, NR / 64);
        mix5_kernel<<<grid, 256, MIX5_SMEM>>>(x, xx, tb, maa_w2,
            maa_w, maa_k, maa_v, maa_r, maa_g, xw, xk, xv, xr, xg);
    }

    dim3 gcc(6, NR / 128);   // N=768
    gemm_kernel<0, true><<<gcc, 256>>>(xr, CDIM, W_r, rb, CDIM, CDIM, CDIM, nullptr);
    gemm_kernel<0, true><<<gcc, 256>>>(xk, CDIM, W_k, kb, CDIM, CDIM, CDIM, nullptr);
    gemm_kernel<0, true><<<gcc, 256>>>(xv, CDIM, W_v, vb, CDIM, CDIM, CDIM, nullptr);
    gemm_kernel<2, true><<<gcc, 256>>>(xg, CDIM, W_g, gb, CDIM, CDIM, CDIM, nullptr);

    // h1 = tanh(xw @ dec_w1)  [NR,64]
    {
        dim3 grid(1, NR / 128);
        gemm_kernel<1, false><<<grid, 256>>>(xw, CDIM, dec_w1, h1, 64, 64, CDIM, nullptr);
    }
    // w = time_decay + h1 @ dec_w2  [NR,768]
    gemm_kernel<3, false><<<gcc, 256>>>(h1, 64, dec_w2, wb, CDIM, CDIM, 64, time_decay);

    // WKV6
    wkv6_kernel<<<8 * NHEAD, 256>>>(rb, kb, vb, wb, faaaa, yb);

    // GroupNorm * g
    gn_mul_kernel<<<NR, 384>>>(yb, ln_w, ln_b, gb, yg);

    // out = yg @ W_o.T
    gemm_kernel<0, true><<<gcc, 256>>>(yg, CDIM, W_o, out, CDIM, CDIM, CDIM, nullptr);
}

// round 4
// speedup vs baseline: 1.7849x; 1.7849x over previous
#include <cuda_runtime.h>
#include <math.h>

#define TDIM 1024
#define CDIM 768
#define PH 32
#define PW 32
#define NHEAD 12
#define HS 64
#define NR (8*1024)

__device__ float g_xx [NR*CDIM];
__device__ float g_xxx[NR*CDIM];
__device__ float g_t  [NR*160];
__device__ float g_xw [NR*CDIM];
__device__ float g_xk [NR*CDIM];
__device__ float g_xv [NR*CDIM];
__device__ float g_xr [NR*CDIM];
__device__ float g_xg [NR*CDIM];
__device__ float g_r  [NR*CDIM];
__device__ float g_k  [NR*CDIM];
__device__ float g_v  [NR*CDIM];
__device__ float g_g  [NR*CDIM];
__device__ float g_h1 [NR*64];
__device__ float g_w  [NR*CDIM];
__device__ float g_y  [NR*CDIM];
__device__ float g_yg [NR*CDIM];
__device__ float g_Wc [5*CDIM*CDIM];   // tf32-rounded weights

__device__ __forceinline__ float tf32r(float x) {
    unsigned u;
    asm("cvt.rna.tf32.f32 %0, %1;" : "=r"(u) : "f"(x));
    return __uint_as_float(u);
}

__device__ __forceinline__ void cp16(void* dst, const void* src) {
    unsigned d = (unsigned)__cvta_generic_to_shared(dst);
    asm volatile("cp.async.cg.shared.global [%0], [%1], 16;" :: "r"(d), "l"(src) : "memory");
}

// ---------------- K0: round 5 weight matrices to tf32 ----------------
__global__ void round_w_kernel(const float* __restrict__ w0, const float* __restrict__ w1,
                               const float* __restrict__ w2, const float* __restrict__ w3,
                               const float* __restrict__ w4, float* __restrict__ out)
{
    int idx = blockIdx.x * blockDim.x + threadIdx.x;
    const int NW = CDIM * CDIM;
    if (idx >= 5 * NW) return;
    int m = idx / NW, r = idx % NW;
    const float* src = (m == 0) ? w0 : (m == 1) ? w1 : (m == 2) ? w2 : (m == 3) ? w3 : w4;
    out[idx] = tf32r(src[r]);
}

// ---------------- K1: q_shift + maa_x mix ----------------
__global__ void shift_mix_kernel(const float* __restrict__ x,
                                 const float* __restrict__ maa_x,
                                 float* __restrict__ xx, float* __restrict__ xxx,
                                 int total)
{
    int idx = blockIdx.x * blockDim.x + threadIdx.x;
    if (idx >= total) return;
    int c = idx % CDIM;
    int t = (idx / CDIM) % TDIM;
    int b = idx / (CDIM * TDIM);
    int d  = c & (HS - 1);
    int hh = t >> 5, ww = t & 31;
    float sh = 0.f;
    int st = -1;
    if (d < 16)      { if (ww >= 1)      st = t - 1;  }
    else if (d < 32) { if (ww < PW - 1)  st = t + 1;  }
    else if (d < 48) { if (hh >= 1)      st = t - PW; }
    else             { if (hh < PH - 1)  st = t + PW; }
    if (st >= 0) sh = x[((size_t)b * TDIM + st) * CDIM + c];
    float xv = x[idx];
    float dd = sh - xv;
    xx[idx]  = dd;
    xxx[idx] = xv + dd * maa_x[c];
}

// ---------------- fp32 GEMM (LoRA paths only) ----------------
template<int EPI>
__device__ __forceinline__ float epi_f(float a, const float* bias, int n) {
    if (EPI == 1) return tanhf(a);
    if (EPI == 2) return fmaxf(a, 0.f);
    if (EPI == 3) return a + bias[n];
    return a;
}

template<int EPI, bool BT>
__global__ __launch_bounds__(256, 2) void gemm_kernel(
    const float* __restrict__ A, int lda,
    const float* __restrict__ Bm,
    float* __restrict__ Cm, int ldc,
    int N, int K, const float* __restrict__ bias)
{
    __shared__ __align__(16) float As[16][128];
    __shared__ __align__(16) float Bs[16][132];
    int tid = threadIdx.x;
    int m0 = blockIdx.y * 128, n0 = blockIdx.x * 128;
    int tx = tid & 15, ty = tid >> 4;

    float acc[8][8];
#pragma unroll
    for (int i = 0; i < 8; i++)
#pragma unroll
        for (int j = 0; j < 8; j++) acc[i][j] = 0.f;

    for (int k0 = 0; k0 < K; k0 += 16) {
#pragma unroll
        for (int p = 0; p < 2; p++) {
            int idx = tid + p * 256;
            int r = idx >> 2, kk = (idx & 3) << 2;
            const float4 v = *(const float4*)(A + (size_t)(m0 + r) * lda + k0 + kk);
            As[kk + 0][r] = v.x; As[kk + 1][r] = v.y;
            As[kk + 2][r] = v.z; As[kk + 3][r] = v.w;
        }
        if (BT) {
#pragma unroll
            for (int p = 0; p < 2; p++) {
                int idx = tid + p * 256;
                int r = idx >> 2, kk = (idx & 3) << 2;
                float4 v = make_float4(0.f, 0.f, 0.f, 0.f);
                if (n0 + r < N)
                    v = *(const float4*)(Bm + (size_t)(n0 + r) * K + k0 + kk);
                Bs[kk + 0][r] = v.x; Bs[kk + 1][r] = v.y;
                Bs[kk + 2][r] = v.z; Bs[kk + 3][r] = v.w;
            }
        } else {
#pragma unroll
            for (int p = 0; p < 2; p++) {
                int idx = tid + p * 256;
                int kk = idx >> 5, nn = (idx & 31) << 2;
                float4 v = make_float4(0.f, 0.f, 0.f, 0.f);
                if (n0 + nn < N)
                    v = *(const float4*)(Bm + (size_t)(k0 + kk) * N + n0 + nn);
                Bs[kk][nn + 0] = v.x; Bs[kk][nn + 1] = v.y;
                Bs[kk][nn + 2] = v.z; Bs[kk][nn + 3] = v.w;
            }
        }
        __syncthreads();
#pragma unroll
        for (int kk = 0; kk < 16; kk++) {
            float a[8], b[8];
            *(float4*)&a[0] = *(const float4*)&As[kk][ty * 8];
            *(float4*)&a[4] = *(const float4*)&As[kk][ty * 8 + 4];
            *(float4*)&b[0] = *(const float4*)&Bs[kk][tx * 8];
            *(float4*)&b[4] = *(const float4*)&Bs[kk][tx * 8 + 4];
#pragma unroll
            for (int i = 0; i < 8; i++)
#pragma unroll
                for (int j = 0; j < 8; j++)
                    acc[i][j] += a[i] * b[j];
        }
        __syncthreads();
    }
#pragma unroll
    for (int i = 0; i < 8; i++) {
        int m = m0 + ty * 8 + i;
#pragma unroll
        for (int j4 = 0; j4 < 2; j4++) {
            int n = n0 + tx * 8 + j4 * 4;
            if (n < N) {
                float4 v;
                v.x = epi_f<EPI>(acc[i][j4 * 4 + 0], bias, n + 0);
                v.y = epi_f<EPI>(acc[i][j4 * 4 + 1], bias, n + 1);
                v.z = epi_f<EPI>(acc[i][j4 * 4 + 2], bias, n + 2);
                v.w = epi_f<EPI>(acc[i][j4 * 4 + 3], bias, n + 3);
                *(float4*)(Cm + (size_t)m * ldc + n) = v;
            }
        }
    }
}

// ---------------- tf32 tensor-core GEMM: C[8192,768] = A[8192,768] @ B[768,768]^T ----------------
// A,B pre-rounded to tf32-representable fp32. EPI: 0 none, 2 relu.
#define GT_K   CDIM
#define GT_N   CDIM
#define ASTR   36
#define ASZ    (128*ASTR)
#define GT_SMEM (4*ASZ*4)   // 2 stages x (A+B) = 73728 B

__device__ __forceinline__ void gt_issue(float* sm, const float* __restrict__ A,
                                         const float* __restrict__ Bm,
                                         int m0, int n0, int it, int tid)
{
    int s = it & 1;
    float* As = sm + s * ASZ;
    float* Bs = sm + 2 * ASZ + s * ASZ;
    int k0 = it * 32;
#pragma unroll
    for (int p = 0; p < 4; p++) {
        int c = tid + p * 256;
        int row = c >> 3, kc = (c & 7) << 2;
        cp16(As + row * ASTR + kc, A + (size_t)(m0 + row) * GT_K + k0 + kc);
    }
#pragma unroll
    for (int p = 0; p < 4; p++) {
        int c = tid + p * 256;
        int row = c >> 3, kc = (c & 7) << 2;
        cp16(Bs + row * ASTR + kc, Bm + (size_t)(n0 + row) * GT_K + k0 + kc);
    }
    asm volatile("cp.async.commit_group;" ::: "memory");
}

template<int EPI>
__global__ __launch_bounds__(256) void gemm_tf32_kernel(
    const float* __restrict__ A, const float* __restrict__ Bm,
    float* __restrict__ Cm)
{
    extern __shared__ __align__(16) float sm[];
    int tid = threadIdx.x;
    int lane = tid & 31, warp = tid >> 5;
    int warp_m = warp >> 2, warp_n = warp & 3;   // 2 x 4
    int m0 = blockIdx.y * 128, n0 = blockIdx.x * 128;

    // ldmatrix per-lane source rows
    int lrow = lane & 7;
    int a_m = ((lane >> 3) & 1) * 8 + lrow;
    int a_k = (lane >> 4) * 4;
    int b_k = ((lane >> 3) & 1) * 4;

    float acc[4][4][4];
#pragma unroll
    for (int i = 0; i < 4; i++)
#pragma unroll
        for (int j = 0; j < 4; j++)
#pragma unroll
            for (int q = 0; q < 4; q++) acc[i][j][q] = 0.f;

    gt_issue(sm, A, Bm, m0, n0, 0, tid);

    const int NIT = GT_K / 32;   // 24
#pragma unroll 1
    for (int it = 0; it < NIT; it++) {
        if (it + 1 < NIT) {
            gt_issue(sm, A, Bm, m0, n0, it + 1, tid);
            asm volatile("cp.async.wait_group 1;" ::: "memory");
        } else {
            asm volatile("cp.async.wait_group 0;" ::: "memory");
        }
        __syncthreads();
        int s = it & 1;
        const float* As = sm + s * ASZ;
        const float* Bs = sm + 2 * ASZ + s * ASZ;
#pragma unroll
        for (int ks = 0; ks < 4; ks++) {
            unsigned af[4][4], bf[4][2];
#pragma unroll
            for (int mi = 0; mi < 4; mi++) {
                const float* p = As + (warp_m * 64 + mi * 16 + a_m) * ASTR + ks * 8 + a_k;
                unsigned ad = (unsigned)__cvta_generic_to_shared(p);
                asm volatile("ldmatrix.sync.aligned.m8n8.x4.shared.b16 {%0,%1,%2,%3}, [%4];"
                    : "=r"(af[mi][0]), "=r"(af[mi][1]), "=r"(af[mi][2]), "=r"(af[mi][3]) : "r"(ad));
            }
#pragma unroll
            for (int ni = 0; ni < 4; ni++) {
                const float* p = Bs + (warp_n * 32 + ni * 8 + lrow) * ASTR + ks * 8 + b_k;
                unsigned ad = (unsigned)__cvta_generic_to_shared(p);
                asm volatile("ldmatrix.sync.aligned.m8n8.x2.shared.b16 {%0,%1}, [%2];"
                    : "=r"(bf[ni][0]), "=r"(bf[ni][1]) : "r"(ad));
            }
#pragma unroll
            for (int mi = 0; mi < 4; mi++)
#pragma unroll
                for (int ni = 0; ni < 4; ni++) {
                    asm volatile(
                        "mma.sync.aligned.m16n8k8.row.col.f32.tf32.tf32.f32 "
                        "{%0,%1,%2,%3}, {%4,%5,%6,%7}, {%8,%9}, {%0,%1,%2,%3};"
                        : "+f"(acc[mi][ni][0]), "+f"(acc[mi][ni][1]),
                          "+f"(acc[mi][ni][2]), "+f"(acc[mi][ni][3])
                        : "r"(af[mi][0]), "r"(af[mi][1]), "r"(af[mi][2]), "r"(af[mi][3]),
                          "r"(bf[ni][0]), "r"(bf[ni][1]));
                }
        }
        __syncthreads();
    }

    // epilogue
    int erow = lane >> 2, ecol = (lane & 3) * 2;
#pragma unroll
    for (int mi = 0; mi < 4; mi++) {
#pragma unroll
        for (int ni = 0; ni < 4; ni++) {
            int m = m0 + warp_m * 64 + mi * 16 + erow;
            int n = n0 + warp_n * 32 + ni * 8 + ecol;
            float2 v0, v1;
            v0.x = epi_f<EPI>(acc[mi][ni][0], nullptr, 0);
            v0.y = epi_f<EPI>(acc[mi][ni][1], nullptr, 0);
            v1.x = epi_f<EPI>(acc[mi][ni][2], nullptr, 0);
            v1.y = epi_f<EPI>(acc[mi][ni][3], nullptr, 0);
            *(float2*)(Cm + (size_t)m * GT_N + n) = v0;
            *(float2*)(Cm + (size_t)(m + 8) * GT_N + n) = v1;
        }
    }
}

// ---------------- K3: 5-way token-shift mixer (rounds xr/xk/xv/xg to tf32) ----------------
#define MIX5_SMEM ((160*256 + 8*160) * 4)
__global__ __launch_bounds__(256, 1) void mix5_kernel(
    const float* __restrict__ x, const float* __restrict__ xx,
    const float* __restrict__ t_arr, const float* __restrict__ w2,
    const float* __restrict__ mw, const float* __restrict__ mk,
    const float* __restrict__ mv, const float* __restrict__ mr,
    const float* __restrict__ mg,
    float* __restrict__ xw, float* __restrict__ xk, float* __restrict__ xv,
    float* __restrict__ xr, float* __restrict__ xg)
{
    extern __shared__ __align__(16) float sm[];
    float* w2s = sm;
    float* ts2 = sm + 160 * 256;
    int tid = threadIdx.x;
    int c = blockIdx.x * 256 + tid;
    int rbase = blockIdx.y * 64;

    for (int j = 0; j < 160; j++) w2s[j * 256 + tid] = w2[j * CDIM + c];
    float cw = mw[c], ck = mk[c], cv = mv[c], cr = mr[c], cg = mg[c];
    __syncthreads();

#pragma unroll 1
    for (int grp = 0; grp < 8; grp++) {
        int row0 = rbase + grp * 8;
        for (int i = tid; i < 8 * 160; i += 256)
            ts2[i] = t_arr[(size_t)(row0 + i / 160) * 160 + (i % 160)];
        __syncthreads();

        float acc[8][5];
#pragma unroll
        for (int r = 0; r < 8; r++)
#pragma unroll
            for (int f = 0; f < 5; f++) acc[r][f] = 0.f;

#pragma unroll
        for (int f = 0; f < 5; f++) {
#pragma unroll 2
            for (int j4 = 0; j4 < 8; j4++) {
                int jb = f * 32 + j4 * 4;
                float w0 = w2s[(jb + 0) * 256 + tid];
                float w1 = w2s[(jb + 1) * 256 + tid];
                float w2v = w2s[(jb + 2) * 256 + tid];
                float w3 = w2s[(jb + 3) * 256 + tid];
#pragma unroll
                for (int r = 0; r < 8; r++) {
                    float4 tv = *(const float4*)&ts2[r * 160 + jb];
                    acc[r][f] += tv.x * w0 + tv.y * w1 + tv.z * w2v + tv.w * w3;
                }
            }
        }
#pragma unroll
        for (int r = 0; r < 8; r++) {
            size_t gi = (size_t)(row0 + r) * CDIM + c;
            float xval = x[gi], xxval = xx[gi];
            xw[gi] = xval + xxval * (cw + acc[r][0]);
            xk[gi] = tf32r(xval + xxval * (ck + acc[r][1]));
            xv[gi] = tf32r(xval + xxval * (cv + acc[r][2]));
            xr[gi] = tf32r(xval + xxval * (cr + acc[r][3]));
            xg[gi] = tf32r(xval + xxval * (cg + acc[r][4]));
        }
        __syncthreads();
    }
}

// ---------------- K4: WKV6 recurrence ----------------
__device__ __forceinline__ void wkv_issue(int ci, float* rsb, float* ksb,
        float* vsb, float* wsb,
        const float* rp, const float* kp, const float* vp, const float* wpp,
        size_t base, int tid)
{
#pragma unroll
    for (int p = 0; p < 2; p++) {
        int idx = tid + p * 256;
        int arr = idx >> 7;
        int rem = idx & 127;
        int tc = rem >> 4, c4 = (rem & 15) << 2;
        size_t gofs = base + (size_t)(ci * 8 + tc) * CDIM + c4;
        float* dst; const float* src;
        if (arr == 0)      { dst = rsb + tc * 64 + c4; src = rp  + gofs; }
        else if (arr == 1) { dst = ksb + tc * 64 + c4; src = kp  + gofs; }
        else if (arr == 2) { dst = vsb + tc * 64 + c4; src = vp  + gofs; }
        else               { dst = wsb + tc * 64 + c4; src = wpp + gofs; }
        cp16(dst, src);
    }
    asm volatile("cp.async.commit_group;" ::: "memory");
}

__global__ __launch_bounds__(256, 1) void wkv6_kernel(
    const float* __restrict__ rp, const float* __restrict__ kp,
    const float* __restrict__ vp, const float* __restrict__ wp_,
    const float* __restrict__ up, float* __restrict__ yp)
{
    __shared__ __align__(16) float rs[2][512], ks[2][512], vs[2][512], ws[2][512];
    __shared__ float us[64], ruks[8];
    int tid = threadIdx.x;
    int b = blockIdx.x / NHEAD, h = blockIdx.x % NHEAD;
    size_t base = (size_t)b * TDIM * CDIM + h * HS;
    if (tid < 64) us[tid] = up[h * HS + tid];
    int i = tid >> 2, jq = tid & 3;
    int lane = tid & 31, warp = tid >> 5;

    float S[16];
#pragma unroll
    for (int q = 0; q < 16; q++) S[q] = 0.f;

    wkv_issue(0, rs[0], ks[0], vs[0], ws[0], rp, kp, vp, wp_, base, tid);

#pragma unroll 1
    for (int ci = 0; ci < TDIM / 8; ci++) {
        int buf = ci & 1;
        asm volatile("cp.async.wait_group 0;" ::: "memory");
        __syncthreads();
        for (int idx = tid; idx < 512; idx += 256)
            ws[buf][idx] = expf(-expf(ws[buf][idx]));
        {
            float p = rs[buf][warp * 64 + lane] * us[lane] * ks[buf][warp * 64 + lane]
                    + rs[buf][warp * 64 + 32 + lane] * us[32 + lane] * ks[buf][warp * 64 + 32 + lane];
#pragma unroll
            for (int o = 16; o; o >>= 1) p += __shfl_xor_sync(0xffffffffu, p, o);
            if (lane == 0) ruks[warp] = p;
        }
        __syncthreads();
        if (ci + 1 < TDIM / 8) {
            int nb = buf ^ 1;
            wkv_issue(ci + 1, rs[nb], ks[nb], vs[nb], ws[nb], rp, kp, vp, wp_, base, tid);
        }
#pragma unroll 1
        for (int tc = 0; tc < 8; tc++) {
            float vi = vs[buf][tc * 64 + i];
            const float4* r4 = (const float4*)&rs[buf][tc * 64 + jq * 16];
            const float4* k4 = (const float4*)&ks[buf][tc * 64 + jq * 16];
            const float4* w4 = (const float4*)&ws[buf][tc * 64 + jq * 16];
            float yps = 0.f;
#pragma unroll
            for (int q = 0; q < 4; q++) {
                float4 rv = r4[q], kv = k4[q], wv = w4[q];
                yps += rv.x * S[q * 4 + 0]; S[q * 4 + 0] = wv.x * S[q * 4 + 0] + kv.x * vi;
                yps += rv.y * S[q * 4 + 1]; S[q * 4 + 1] = wv.y * S[q * 4 + 1] + kv.y * vi;
                yps += rv.z * S[q * 4 + 2]; S[q * 4 + 2] = wv.z * S[q * 4 + 2] + kv.z * vi;
                yps += rv.w * S[q * 4 + 3]; S[q * 4 + 3] = wv.w * S[q * 4 + 3] + kv.w * vi;
            }
            yps += __shfl_xor_sync(0xffffffffu, yps, 1);
            yps += __shfl_xor_sync(0xffffffffu, yps, 2);
            if (jq == 0)
                yp[base + (size_t)(ci * 8 + tc) * CDIM + i] = yps + vi * ruks[tc];
        }
    }
}

// ---------------- K5: per-head GroupNorm * g (rounds to tf32) ----------------
__global__ void gn_mul_kernel(const float* __restrict__ y,
                              const float* __restrict__ lw, const float* __restrict__ lb,
                              const float* __restrict__ g, float* __restrict__ out)
{
    int row = blockIdx.x;
    int warp = threadIdx.x >> 5, lane = threadIdx.x & 31;
    size_t o = (size_t)row * CDIM + warp * HS;
    float v0 = y[o + lane], v1 = y[o + 32 + lane];
    float s = v0 + v1, ss = v0 * v0 + v1 * v1;
#pragma unroll
    for (int off = 16; off; off >>= 1) {
        s  += __shfl_xor_sync(0xffffffffu, s,  off);
        ss += __shfl_xor_sync(0xffffffffu, ss, off);
    }
    float mean = s * (1.f / HS);
    float var  = ss * (1.f / HS) - mean * mean;
    float inv  = rsqrtf(var + 1e-5f);
    int c0 = warp * HS + lane, c1 = c0 + 32;
    float n0 = (v0 - mean) * inv * lw[c0] + lb[c0];
    float n1 = (v1 - mean) * inv * lw[c1] + lb[c1];
    out[o + lane]      = tf32r(n0 * g[o + lane]);
    out[o + 32 + lane] = tf32r(n1 * g[o + 32 + lane]);
}

// ---------------- launcher ----------------
extern "C" void kernel_launch(void* const* d_in, const int* in_sizes, int n_in,
                              void* d_out, int out_size)
{
    const float* x          = (const float*)d_in[0];
    const float* W_r        = (const float*)d_in[1];
    const float* W_k        = (const float*)d_in[2];
    const float* W_v        = (const float*)d_in[3];
    const float* W_g        = (const float*)d_in[4];
    const float* W_o        = (const float*)d_in[5];
    const float* maa_x      = (const float*)d_in[6];
    const float* maa_w      = (const float*)d_in[7];
    const float* maa_k      = (const float*)d_in[8];
    const float* maa_v      = (const float*)d_in[9];
    const float* maa_r      = (const float*)d_in[10];
    const float* maa_g      = (const float*)d_in[11];
    const float* maa_w1     = (const float*)d_in[12];
    const float* maa_w2     = (const float*)d_in[13];
    const float* time_decay = (const float*)d_in[14];
    const float* dec_w1     = (const float*)d_in[15];
    const float* dec_w2     = (const float*)d_in[16];
    const float* faaaa      = (const float*)d_in[17];
    const float* ln_w       = (const float*)d_in[18];
    const float* ln_b       = (const float*)d_in[19];
    float* out = (float*)d_out;

    float *xx, *xxx, *tb, *xw, *xk, *xv, *xr, *xg, *rb, *kb, *vb, *gb, *h1, *wb, *yb, *yg, *Wc;
    cudaGetSymbolAddress((void**)&xx,  g_xx);
    cudaGetSymbolAddress((void**)&xxx, g_xxx);
    cudaGetSymbolAddress((void**)&tb,  g_t);
    cudaGetSymbolAddress((void**)&xw,  g_xw);
    cudaGetSymbolAddress((void**)&xk,  g_xk);
    cudaGetSymbolAddress((void**)&xv,  g_xv);
    cudaGetSymbolAddress((void**)&xr,  g_xr);
    cudaGetSymbolAddress((void**)&xg,  g_xg);
    cudaGetSymbolAddress((void**)&rb,  g_r);
    cudaGetSymbolAddress((void**)&kb,  g_k);
    cudaGetSymbolAddress((void**)&vb,  g_v);
    cudaGetSymbolAddress((void**)&gb,  g_g);
    cudaGetSymbolAddress((void**)&h1,  g_h1);
    cudaGetSymbolAddress((void**)&wb,  g_w);
    cudaGetSymbolAddress((void**)&yb,  g_y);
    cudaGetSymbolAddress((void**)&yg,  g_yg);
    cudaGetSymbolAddress((void**)&Wc,  g_Wc);

    const int NW = CDIM * CDIM;
    float* Wr_c = Wc + 0 * NW;
    float* Wk_c = Wc + 1 * NW;
    float* Wv_c = Wc + 2 * NW;
    float* Wg_c = Wc + 3 * NW;
    float* Wo_c = Wc + 4 * NW;

    cudaFuncSetAttribute(mix5_kernel, cudaFuncAttributeMaxDynamicSharedMemorySize, MIX5_SMEM);
    cudaFuncSetAttribute(gemm_tf32_kernel<0>, cudaFuncAttributeMaxDynamicSharedMemorySize, GT_SMEM);
    cudaFuncSetAttribute(gemm_tf32_kernel<2>, cudaFuncAttributeMaxDynamicSharedMemorySize, GT_SMEM);

    round_w_kernel<<<(5 * NW + 255) / 256, 256>>>(W_r, W_k, W_v, W_g, W_o, Wc);

    int total = NR * CDIM;
    shift_mix_kernel<<<(total + 255) / 256, 256>>>(x, maa_x, xx, xxx, total);

    // t = tanh(xxx @ maa_w1)   [NR,160]
    {
        dim3 grid(2, NR / 128);
        gemm_kernel<1, false><<<grid, 256>>>(xxx, CDIM, maa_w1, tb, 160, 160, CDIM, nullptr);
    }

    // xw..xg via 5-way mixer
    {
        dim3 grid(3, NR / 64);
        mix5_kernel<<<grid, 256, MIX5_SMEM>>>(x, xx, tb, maa_w2,
            maa_w, maa_k, maa_v, maa_r, maa_g, xw, xk, xv, xr, xg);
    }

    dim3 gtc(6, NR / 128);
    gemm_tf32_kernel<0><<<gtc, 256, GT_SMEM>>>(xr, Wr_c, rb);
    gemm_tf32_kernel<0><<<gtc, 256, GT_SMEM>>>(xk, Wk_c, kb);
    gemm_tf32_kernel<0><<<gtc, 256, GT_SMEM>>>(xv, Wv_c, vb);
    gemm_tf32_kernel<2><<<gtc, 256, GT_SMEM>>>(xg, Wg_c, gb);

    // h1 = tanh(xw @ dec_w1)  [NR,64]
    {
        dim3 grid(1, NR / 128);
        gemm_kernel<1, false><<<grid, 256>>>(xw, CDIM, dec_w1, h1, 64, 64, CDIM, nullptr);
    }
    // w = time_decay + h1 @ dec_w2  [NR,768]
    {
        dim3 gcc(6, NR / 128);
        gemm_kernel<3, false><<<gcc, 256>>>(h1, 64, dec_w2, wb, CDIM, CDIM, 64, time_decay);
    }

    // WKV6
    wkv6_kernel<<<8 * NHEAD, 256>>>(rb, kb, vb, wb, faaaa, yb);

    // GroupNorm * g
    gn_mul_kernel<<<NR, 384>>>(yb, ln_w, ln_b, gb, yg);

    // out = yg @ W_o.T
    gemm_tf32_kernel<0><<<gtc, 256, GT_SMEM>>>(yg, Wo_c, out);
}